// round 9
// baseline (speedup 1.0000x reference)
#include <cuda_runtime.h>
#include <cstdint>

#define N_ROWS 512
#define D_COLS 256
#define GROUPS 8                 // column groups, 32 cols (one 128B line) each
#define RBLKS  4                 // row-blocks of 128 rows
#define NBLK   (GROUPS * RBLKS)  // 32
#define THREADS 512

// Global state: per-group column stats + ONE ticket. Zeroed at module load;
// the finisher resets everything each call (graph-replay safe).
__device__ float gStats[GROUPS][5][32];   // [group][stat][col] 5 KB
__device__ unsigned int gTicket;

#define SHFL4(v, s) do {                                   \
    (v).x += __shfl_xor_sync(0xFFFFFFFFu, (v).x, (s));     \
    (v).y += __shfl_xor_sync(0xFFFFFFFFu, (v).y, (s));     \
    (v).z += __shfl_xor_sync(0xFFFFFFFFu, (v).z, (s));     \
    (v).w += __shfl_xor_sync(0xFFFFFFFFu, (v).w, (s)); } while (0)

__global__ void __launch_bounds__(THREADS)
club_tile2d_flat(const float* __restrict__ mu,
                 const float* __restrict__ logvar,
                 const float* __restrict__ h,
                 float* __restrict__ out) {
    const int tid  = threadIdx.x;
    const int lane = tid & 31;
    const int w    = tid >> 5;              // warp 0..15
    const int g    = blockIdx.x >> 2;       // column group 0..7
    const int rb   = blockIdx.x & 3;        // row block 0..3
    const int q    = tid & 7;               // col quad 0..7 (4 cols)
    const int rs   = tid >> 3;              // row slot 0..63

    const float4* __restrict__ h4 = (const float4*)h;
    const float4* __restrict__ m4 = (const float4*)mu;
    const float4* __restrict__ l4 = (const float4*)logvar;

    // ---- Phase 1: 2 rows x float4; warp-LDG = 4 dense 128B lines ----
    float4 s1 = {0,0,0,0}, s2 = {0,0,0,0}, a = {0,0,0,0},
           b  = {0,0,0,0}, c  = {0,0,0,0};

#define ACC_C(C) {                                          \
        const float iv = __expf(-lv.C);                     \
        s1.C += hv.C;                                       \
        s2.C += hv.C * hv.C;                                \
        a.C  += iv * mv.C;                                  \
        b.C  += iv;                                         \
        c.C  += iv * hv.C * (hv.C - 2.0f * mv.C); }

#pragma unroll
    for (int p = 0; p < 2; ++p) {
        const int row = rb * 128 + rs + p * 64;
        const int i4  = row * (D_COLS / 4) + g * 8 + q;
        const float4 hv = h4[i4];
        const float4 mv = m4[i4];
        const float4 lv = l4[i4];
        ACC_C(x); ACC_C(y); ACC_C(z); ACC_C(w);
    }
#undef ACC_C

    // ---- Phase 2: reduce the warp's 4 row-slots (xor 8,16 keeps quad) ----
    SHFL4(s1, 8);  SHFL4(s2, 8);  SHFL4(a, 8);  SHFL4(b, 8);  SHFL4(c, 8);
    SHFL4(s1, 16); SHFL4(s2, 16); SHFL4(a, 16); SHFL4(b, 16); SHFL4(c, 16);

    // ---- Phase 3: 16 warps publish; warp 0 combines the block ----
    __shared__ float4 part[16][5][9];       // padded rows vs bank conflicts
    if (lane < 8) {
        part[w][0][lane] = s1; part[w][1][lane] = s2; part[w][2][lane] = a;
        part[w][3][lane] = b;  part[w][4][lane] = c;
    }
    __syncthreads();
    if (w != 0) return;

    const int q2 = lane & 7;
    const int k  = lane >> 3;               // 0..3
    float4 S1 = {0,0,0,0}, S2 = {0,0,0,0}, A = {0,0,0,0},
           B  = {0,0,0,0}, C  = {0,0,0,0};
#pragma unroll
    for (int j = 0; j < 4; ++j) {
        const int ww = k + 4 * j;
        const float4 v0 = part[ww][0][q2]; S1.x+=v0.x; S1.y+=v0.y; S1.z+=v0.z; S1.w+=v0.w;
        const float4 v1 = part[ww][1][q2]; S2.x+=v1.x; S2.y+=v1.y; S2.z+=v1.z; S2.w+=v1.w;
        const float4 v2 = part[ww][2][q2]; A.x +=v2.x; A.y +=v2.y; A.z +=v2.z; A.w +=v2.w;
        const float4 v3 = part[ww][3][q2]; B.x +=v3.x; B.y +=v3.y; B.z +=v3.z; B.w +=v3.w;
        const float4 v4 = part[ww][4][q2]; C.x +=v4.x; C.y +=v4.y; C.z +=v4.z; C.w +=v4.w;
    }
    SHFL4(S1, 8);  SHFL4(S2, 8);  SHFL4(A, 8);  SHFL4(B, 8);  SHFL4(C, 8);
    SHFL4(S1, 16); SHFL4(S2, 16); SHFL4(A, 16); SHFL4(B, 16); SHFL4(C, 16);

    // ---- Phase 4: fire-and-forget REDG of the block's 160 stat floats ----
    if (lane < 8) {
        const int c0 = q2 * 4;
        atomicAdd(&gStats[g][0][c0+0], S1.x); atomicAdd(&gStats[g][0][c0+1], S1.y);
        atomicAdd(&gStats[g][0][c0+2], S1.z); atomicAdd(&gStats[g][0][c0+3], S1.w);
        atomicAdd(&gStats[g][1][c0+0], S2.x); atomicAdd(&gStats[g][1][c0+1], S2.y);
        atomicAdd(&gStats[g][1][c0+2], S2.z); atomicAdd(&gStats[g][1][c0+3], S2.w);
        atomicAdd(&gStats[g][2][c0+0], A.x);  atomicAdd(&gStats[g][2][c0+1], A.y);
        atomicAdd(&gStats[g][2][c0+2], A.z);  atomicAdd(&gStats[g][2][c0+3], A.w);
        atomicAdd(&gStats[g][3][c0+0], B.x);  atomicAdd(&gStats[g][3][c0+1], B.y);
        atomicAdd(&gStats[g][3][c0+2], B.z);  atomicAdd(&gStats[g][3][c0+3], B.w);
        atomicAdd(&gStats[g][4][c0+0], C.x);  atomicAdd(&gStats[g][4][c0+1], C.y);
        atomicAdd(&gStats[g][4][c0+2], C.z);  atomicAdd(&gStats[g][4][c0+3], C.w);
    }
    __syncwarp();   // order all lanes' REDGs before lane0's release

    // ---- Phase 5: ONE global ticket; 32nd arriver does the whole finish ----
    unsigned int old = 0;
    if (lane == 0)
        asm volatile("atom.acq_rel.gpu.global.add.u32 %0, [%1], %2;"
                     : "=r"(old) : "l"(&gTicket), "r"(1u) : "memory");
    old = __shfl_sync(0xFFFFFFFFu, old, 0);   // also propagates acquire order
    if (old != NBLK - 1) return;

    // Readback: 40 coalesced 128B loads (8 groups x 5 stats), L2-pipelined.
    float* gbase = &gStats[0][0][0];
    float v[40];
#pragma unroll
    for (int t = 0; t < 40; ++t)
        v[t] = __ldcg(gbase + t * 32 + lane);

    const float invN = 1.0f / (float)N_ROWS;
    float term = 0.f;
#pragma unroll
    for (int gg = 0; gg < GROUPS; ++gg) {
        const float S1v = v[gg*5+0], S2v = v[gg*5+1], Av = v[gg*5+2],
                    Bv  = v[gg*5+3], Cv  = v[gg*5+4];
        term += Cv + invN * (2.0f * S1v * Av - S2v * Bv);
    }
#pragma unroll
    for (int s = 16; s > 0; s >>= 1)
        term += __shfl_xor_sync(0xFFFFFFFFu, term, s);

    if (lane == 0) out[0] = -0.5f * invN * term;

    // Reset state for the next graph replay (kernel boundary orders this).
#pragma unroll
    for (int t = 0; t < 40; ++t)
        gbase[t * 32 + lane] = 0.f;
    if (lane == 0) gTicket = 0u;
}

extern "C" void kernel_launch(void* const* d_in, const int* in_sizes, int n_in,
                              void* d_out, int out_size) {
    const float* mu     = (const float*)d_in[0];
    const float* logvar = (const float*)d_in[1];
    const float* h      = (const float*)d_in[2];
    float* out          = (float*)d_out;
    club_tile2d_flat<<<NBLK, THREADS>>>(mu, logvar, h, out);
}

// round 10
// speedup vs baseline: 1.3478x; 1.3478x over previous
#include <cuda_runtime.h>
#include <cstdint>

#define N_ROWS 512
#define D_COLS 256
#define NBLK 128                  // one CTA per column pair -> 128 of 148 SMs
#define THREADS 256
#define SCALE_F 16777216.0f       // 2^24 fixed-point scale

// Single word of global state: bits 8..63 = fixed-point sum, bits 0..7 = count
// (128 arrivals < 256). Zeroed at module load; finisher resets each call.
__device__ unsigned long long gPacked;

#define SHFL2(v, s) do {                                   \
    (v).x += __shfl_xor_sync(0xFFFFFFFFu, (v).x, (s));     \
    (v).y += __shfl_xor_sync(0xFFFFFFFFu, (v).y, (s)); } while (0)

__global__ void __launch_bounds__(THREADS)
club_colsplit128(const float* __restrict__ mu,
                 const float* __restrict__ logvar,
                 const float* __restrict__ h,
                 float* __restrict__ out) {
    const int tid  = threadIdx.x;
    const int lane = tid & 31;
    const int w    = tid >> 5;                  // warp 0..7
    const int g    = blockIdx.x;                // column pair: cols 2g, 2g+1

    const float2* __restrict__ h2 = (const float2*)h;
    const float2* __restrict__ m2 = (const float2*)mu;
    const float2* __restrict__ l2 = (const float2*)logvar;

    // ---- Phase 1: 2 rows per thread (rows tid and tid+256), float2 = both
    // columns of this block. All loads independent -> full MLP. ----
    float2 s1 = {0,0}, s2 = {0,0}, a = {0,0}, b = {0,0}, c = {0,0};

#define ACC_C(C) {                                          \
        const float iv = __expf(-lv.C);                     \
        s1.C += hv.C;                                       \
        s2.C += hv.C * hv.C;                                \
        a.C  += iv * mv.C;                                  \
        b.C  += iv;                                         \
        c.C  += iv * hv.C * (hv.C - 2.0f * mv.C); }

#pragma unroll
    for (int p = 0; p < 2; ++p) {
        const int row = tid + p * THREADS;      // 0..511
        const int i2  = row * (D_COLS / 2) + g;
        const float2 hv = h2[i2];
        const float2 mv = m2[i2];
        const float2 lv = l2[i2];
        ACC_C(x); ACC_C(y);
    }
#undef ACC_C

    // ---- Phase 2: full-warp reduction (every lane holds the same 2 cols) ----
#pragma unroll
    for (int s = 16; s > 0; s >>= 1) {
        SHFL2(s1, s); SHFL2(s2, s); SHFL2(a, s); SHFL2(b, s); SHFL2(c, s);
    }

    // ---- Phase 3: 8 warps publish; warp 0 combines and finishes ----
    __shared__ float2 part[8][5];
    if (lane == 0) {
        part[w][0] = s1; part[w][1] = s2; part[w][2] = a;
        part[w][3] = b;  part[w][4] = c;
    }
    __syncthreads();
    if (w != 0) return;

    // Lanes 0..7 each grab one warp's 5 stats; xor 1,2,4 folds the 8 warps.
    float2 S1 = {0,0}, S2 = {0,0}, A = {0,0}, B = {0,0}, C = {0,0};
    if (lane < 8) {
        S1 = part[lane][0]; S2 = part[lane][1]; A = part[lane][2];
        B  = part[lane][3]; C  = part[lane][4];
    }
#pragma unroll
    for (int s = 1; s <= 4; s <<= 1) {
        SHFL2(S1, s); SHFL2(S2, s); SHFL2(A, s); SHFL2(B, s); SHFL2(C, s);
    }

    if (lane == 0) {
        const float invN = 1.0f / (float)N_ROWS;
        const float term =
            (C.x + invN * (2.0f * S1.x * A.x - S2.x * B.x)) +
            (C.y + invN * (2.0f * S1.y * A.y - S2.y * B.y));

        // ONE packed atomic: value (bits 8..63) + arrival count (bits 0..7).
        // The 128th arriver holds the complete sum in old+myv.
        const long long fix = __float2ll_rn(term * SCALE_F);
        const unsigned long long myv = ((unsigned long long)fix << 8) + 1ull;
        const unsigned long long old = atomicAdd(&gPacked, myv);
        if ((old & 255ull) == (unsigned long long)(NBLK - 1)) {
            const long long tot = (long long)(old + myv);   // 256*F + 128
            const long long F   = tot >> 8;                 // exact
            out[0]  = (float)((-0.5 / (double)N_ROWS) *
                              ((double)F * (1.0 / (double)SCALE_F)));
            gPacked = 0ull;                                 // reset for replay
        }
    }
}

extern "C" void kernel_launch(void* const* d_in, const int* in_sizes, int n_in,
                              void* d_out, int out_size) {
    const float* mu     = (const float*)d_in[0];
    const float* logvar = (const float*)d_in[1];
    const float* h      = (const float*)d_in[2];
    float* out          = (float*)d_out;
    club_colsplit128<<<NBLK, THREADS>>>(mu, logvar, h, out);
}